// round 17
// baseline (speedup 1.0000x reference)
#include <cuda_runtime.h>
#include <cuda_fp16.h>

#define S_LEN 2048
#define B_SZ 2
#define NH 16
#define NKV 4
#define HD 128
#define QSTRIDE (NH*HD)      /* 2048 */
#define KSTRIDE (NKV*HD)     /* 512  */
#define SCALE_F 0.08838834764831845f
#define LOG2E   1.44269504088896341f
#define QSC     (SCALE_F*LOG2E)      /* fold softmax scale + log2e into Q */
#define BQ 128
#define BK 128
#define PIT 136              /* smem pitch in halves: 272B rows -> conflict-free LDSM */
#define NTS 64

#define SMEM1 (5*BK*PIT*2)                              /* Q + 2*(K+V) = 174080 B */
#define BK2 256                                         /* kernel2 k-cols per CTA */
#define SMEM2 ((64+BK2)*PIT*2 + (64+64+8*128)*4)        /* 91648 B */

#define NKH (B_SZ*S_LEN*KSTRIDE)   /* 2097152 */

__device__ __half g_kh[NKH];         // K fp16
__device__ __half g_vh[NKH];         // V fp16
__device__ float  g_m[B_SZ*NH*NTS];  // log2-domain row max
__device__ float  g_l[B_SZ*NH*NTS];  // row denom

__device__ __forceinline__ float ex2f(float x) {
    float y;
    asm("ex2.approx.ftz.f32 %0, %1;" : "=f"(y) : "f"(x));
    return y;
}

__device__ __forceinline__ unsigned packh2(float x, float y) {
    half2 t = __floats2half2_rn(x, y);
    return *reinterpret_cast<unsigned*>(&t);
}

__device__ __forceinline__ void mma16816(float& c0, float& c1, float& c2, float& c3,
                                         unsigned a0, unsigned a1, unsigned a2, unsigned a3,
                                         unsigned b0, unsigned b1) {
    asm volatile(
        "mma.sync.aligned.m16n8k16.row.col.f32.f16.f16.f32 "
        "{%0,%1,%2,%3}, {%4,%5,%6,%7}, {%8,%9}, {%0,%1,%2,%3};\n"
        : "+f"(c0), "+f"(c1), "+f"(c2), "+f"(c3)
        : "r"(a0), "r"(a1), "r"(a2), "r"(a3), "r"(b0), "r"(b1));
}

__device__ __forceinline__ void ldsm_x4(unsigned& r0, unsigned& r1, unsigned& r2, unsigned& r3,
                                        const half* p) {
    unsigned a = (unsigned)__cvta_generic_to_shared(p);
    asm volatile("ldmatrix.sync.aligned.m8n8.x4.shared.b16 {%0,%1,%2,%3}, [%4];\n"
                 : "=r"(r0), "=r"(r1), "=r"(r2), "=r"(r3) : "r"(a));
}

__device__ __forceinline__ void ldsm_x4_t(unsigned& r0, unsigned& r1, unsigned& r2, unsigned& r3,
                                          const half* p) {
    unsigned a = (unsigned)__cvta_generic_to_shared(p);
    asm volatile("ldmatrix.sync.aligned.m8n8.x4.trans.shared.b16 {%0,%1,%2,%3}, [%4];\n"
                 : "=r"(r0), "=r"(r1), "=r"(r2), "=r"(r3) : "r"(a));
}

__device__ __forceinline__ unsigned pack2(float x, float y) {
    half2 t = __floats2half2_rn(x, y);
    return *reinterpret_cast<unsigned*>(&t);
}

__device__ __forceinline__ void cp16(const half* smem_dst, const __half* gmem_src) {
    unsigned sa = (unsigned)__cvta_generic_to_shared(smem_dst);
    asm volatile("cp.async.cg.shared.global [%0], [%1], 16;\n"
                 :: "r"(sa), "l"(gmem_src) : "memory");
}
#define CP_COMMIT() asm volatile("cp.async.commit_group;\n" ::: "memory")
#define CP_WAIT0()  asm volatile("cp.async.wait_group 0;\n" ::: "memory")

// ---------------------------------------------------------------------------
// Kernel 0: one-time K/V fp32 -> fp16. Exact-fit grid (no loop; latency-bound).
// ---------------------------------------------------------------------------
__global__ void __launch_bounds__(256) prepass(
    const float* __restrict__ k, const float* __restrict__ v)
{
    int i = blockIdx.x * 256 + threadIdx.x;   // grid sized to NKH/4 exactly
    float4 t = ((const float4*)k)[i];
    ((uint2*)g_kh)[i] = make_uint2(packh2(t.x, t.y), packh2(t.z, t.w));
    float4 s = ((const float4*)v)[i];
    ((uint2*)g_vh)[i] = make_uint2(packh2(s.x, s.y), packh2(s.z, s.w));
}

// ---------------------------------------------------------------------------
// Kernel 1: causal flash attention (fp16 HMMA via ldmatrix, fp32 accum).
// grid (S/128, NH, B), 256 threads (8 warps). Warp w owns q rows [16w,16w+16).
// fp16 K/V double-buffered via cp.async; exp2/pack interleaved with PV mma
// issue; l-sum deferred. (Best measured configuration.)
// ---------------------------------------------------------------------------
__global__ void __launch_bounds__(256, 1) flash_fwd(
    const float* __restrict__ q, float* __restrict__ out)
{
    extern __shared__ __align__(16) half sm[];
    half* Qs   = sm;                 // BQ x PIT
    half* Kbuf = sm + BQ*PIT;        // 2 x (K[BK x PIT] then V[BK x PIT])

    const int qi   = gridDim.x - 1 - blockIdx.x;   // heavy tiles first
    const int h    = blockIdx.y;
    const int b    = blockIdx.z;
    const int hk   = h >> 2;
    const int tid  = threadIdx.x;
    const int w    = tid >> 5;
    const int lane = tid & 31;
    const int q0   = qi * BQ;

    const __half* kb0 = g_kh + (size_t)(b*S_LEN)*KSTRIDE + hk*HD;
    const __half* vb0 = g_vh + (size_t)(b*S_LEN)*KSTRIDE + hk*HD;

    // ---- K/V tile 0 via cp.async ----
    {
        half* Ks = Kbuf;
        half* Vs = Kbuf + BK*PIT;
        #pragma unroll
        for (int i = tid; i < BK*16; i += 256) {
            int r = i >> 4, c = i & 15;
            cp16(&Ks[r*PIT + c*8], kb0 + (size_t)r*KSTRIDE + c*8);
            cp16(&Vs[r*PIT + c*8], vb0 + (size_t)r*KSTRIDE + c*8);
        }
        CP_COMMIT();
    }

    // ---- Q tile fp32 -> smem fp16 (scale*log2e folded; one-time per CTA) ----
    {
        const float* qbase = q + (size_t)(b*S_LEN + q0)*QSTRIDE + h*HD;
        #pragma unroll 4
        for (int i = tid; i < BQ*32; i += 256) {
            int r = i >> 5, c4 = i & 31;
            float4 t = *(const float4*)(qbase + (size_t)r*QSTRIDE + c4*4);
            *(uint2*)&Qs[r*PIT + c4*4] =
                make_uint2(packh2(t.x*QSC, t.y*QSC), packh2(t.z*QSC, t.w*QSC));
        }
    }
    CP_WAIT0();
    __syncthreads();

    // ---- Q fragments, register resident for the whole CTA lifetime ----
    unsigned aq[8][4];
    {
        const half* qp = &Qs[(w*16 + ((lane>>3)&1)*8 + (lane&7))*PIT + (lane>>4)*8];
        #pragma unroll
        for (int kd = 0; kd < 8; kd++)
            ldsm_x4(aq[kd][0], aq[kd][1], aq[kd][2], aq[kd][3], qp + kd*16);
    }

    const int rq  = lane >> 2;
    const int cq  = (lane & 3) * 2;
    const int qg0 = q0 + w*16 + rq;
    const int qg1 = qg0 + 8;

    float m0 = -1e30f, m1 = -1e30f, l0 = 0.f, l1 = 0.f;
    float oacc[16][4];
    #pragma unroll
    for (int nb = 0; nb < 16; nb++) {
        oacc[nb][0] = 0.f; oacc[nb][1] = 0.f; oacc[nb][2] = 0.f; oacc[nb][3] = 0.f;
    }

    const int ntiles = qi + 1;
    int cur = 0;
    for (int jt = 0; jt < ntiles; jt++) {
        const int k0 = jt * BK;
        half* Ks = Kbuf + cur*(2*BK*PIT);
        half* Vs = Ks + BK*PIT;

        // prefetch next tile into the other buffer (fully async)
        if (jt + 1 < ntiles) {
            half* Kn = Kbuf + (cur^1)*(2*BK*PIT);
            half* Vn = Kn + BK*PIT;
            const __half* kbn = kb0 + (size_t)(jt+1)*BK*KSTRIDE;
            const __half* vbn = vb0 + (size_t)(jt+1)*BK*KSTRIDE;
            #pragma unroll
            for (int i = tid; i < BK*16; i += 256) {
                int r = i >> 4, c = i & 15;
                cp16(&Kn[r*PIT + c*8], kbn + (size_t)r*KSTRIDE + c*8);
                cp16(&Vn[r*PIT + c*8], vbn + (size_t)r*KSTRIDE + c*8);
            }
        }
        CP_COMMIT();

        {
            // ---- S = Q K^T ----
            float sacc[16][4];
            #pragma unroll
            for (int nb = 0; nb < 16; nb++) {
                sacc[nb][0] = 0.f; sacc[nb][1] = 0.f; sacc[nb][2] = 0.f; sacc[nb][3] = 0.f;
            }
            const half* kp = Ks + ((lane>>4)*8 + (lane&7))*PIT + ((lane>>3)&1)*8;
            #pragma unroll
            for (int kd = 0; kd < 8; kd++) {
                #pragma unroll
                for (int nbp = 0; nbp < 8; nbp++) {
                    unsigned b0, b1, b2, b3;
                    ldsm_x4(b0, b1, b2, b3, kp + nbp*16*PIT + kd*16);
                    mma16816(sacc[2*nbp  ][0], sacc[2*nbp  ][1], sacc[2*nbp  ][2], sacc[2*nbp  ][3],
                             aq[kd][0], aq[kd][1], aq[kd][2], aq[kd][3], b0, b1);
                    mma16816(sacc[2*nbp+1][0], sacc[2*nbp+1][1], sacc[2*nbp+1][2], sacc[2*nbp+1][3],
                             aq[kd][0], aq[kd][1], aq[kd][2], aq[kd][3], b2, b3);
                }
            }

            // ---- causal mask (only partially-visible tiles) ----
            if (k0 + BK - 1 > q0 + w*16) {
                #pragma unroll
                for (int nb = 0; nb < 16; nb++) {
                    int c = k0 + nb*8 + cq;
                    if (c     > qg0) sacc[nb][0] = -1e30f;
                    if (c + 1 > qg0) sacc[nb][1] = -1e30f;
                    if (c     > qg1) sacc[nb][2] = -1e30f;
                    if (c + 1 > qg1) sacc[nb][3] = -1e30f;
                }
            }

            // ---- row max + rescale (serial part of softmax) ----
            float mx0 = -1e30f, mx1 = -1e30f;
            #pragma unroll
            for (int nb = 0; nb < 16; nb++) {
                mx0 = fmaxf(mx0, fmaxf(sacc[nb][0], sacc[nb][1]));
                mx1 = fmaxf(mx1, fmaxf(sacc[nb][2], sacc[nb][3]));
            }
            mx0 = fmaxf(mx0, __shfl_xor_sync(0xffffffffu, mx0, 1));
            mx0 = fmaxf(mx0, __shfl_xor_sync(0xffffffffu, mx0, 2));
            mx1 = fmaxf(mx1, __shfl_xor_sync(0xffffffffu, mx1, 1));
            mx1 = fmaxf(mx1, __shfl_xor_sync(0xffffffffu, mx1, 2));

            float mn0 = fmaxf(m0, mx0), mn1 = fmaxf(m1, mx1);
            float al0 = ex2f(m0 - mn0), al1 = ex2f(m1 - mn1);
            m0 = mn0; m1 = mn1;

            #pragma unroll
            for (int nb = 0; nb < 16; nb++) {
                oacc[nb][0] *= al0; oacc[nb][1] *= al0;
                oacc[nb][2] *= al1; oacc[nb][3] *= al1;
            }

            // ---- PV with exp2/pack interleaved per kb block ----
            const half* vp = Vs + (((lane>>3)&1)*8 + (lane&7))*PIT + (lane>>4)*8;
            #pragma unroll
            for (int kb = 0; kb < 8; kb++) {
                sacc[2*kb  ][0] = ex2f(sacc[2*kb  ][0] - mn0);
                sacc[2*kb  ][1] = ex2f(sacc[2*kb  ][1] - mn0);
                sacc[2*kb  ][2] = ex2f(sacc[2*kb  ][2] - mn1);
                sacc[2*kb  ][3] = ex2f(sacc[2*kb  ][3] - mn1);
                sacc[2*kb+1][0] = ex2f(sacc[2*kb+1][0] - mn0);
                sacc[2*kb+1][1] = ex2f(sacc[2*kb+1][1] - mn0);
                sacc[2*kb+1][2] = ex2f(sacc[2*kb+1][2] - mn1);
                sacc[2*kb+1][3] = ex2f(sacc[2*kb+1][3] - mn1);
                unsigned a0 = pack2(sacc[2*kb  ][0], sacc[2*kb  ][1]);
                unsigned a1 = pack2(sacc[2*kb  ][2], sacc[2*kb  ][3]);
                unsigned a2 = pack2(sacc[2*kb+1][0], sacc[2*kb+1][1]);
                unsigned a3 = pack2(sacc[2*kb+1][2], sacc[2*kb+1][3]);
                #pragma unroll
                for (int nbp = 0; nbp < 8; nbp++) {
                    unsigned b0, b1, b2, b3;
                    ldsm_x4_t(b0, b1, b2, b3, vp + kb*16*PIT + nbp*16);
                    mma16816(oacc[2*nbp  ][0], oacc[2*nbp  ][1], oacc[2*nbp  ][2], oacc[2*nbp  ][3],
                             a0, a1, a2, a3, b0, b1);
                    mma16816(oacc[2*nbp+1][0], oacc[2*nbp+1][1], oacc[2*nbp+1][2], oacc[2*nbp+1][3],
                             a0, a1, a2, a3, b2, b3);
                }
            }

            // ---- deferred l row-sum (overlaps PV mma drain) ----
            float s0 = 0.f, s1 = 0.f;
            #pragma unroll
            for (int nb = 0; nb < 16; nb++) {
                s0 += sacc[nb][0] + sacc[nb][1];
                s1 += sacc[nb][2] + sacc[nb][3];
            }
            s0 += __shfl_xor_sync(0xffffffffu, s0, 1);
            s0 += __shfl_xor_sync(0xffffffffu, s0, 2);
            s1 += __shfl_xor_sync(0xffffffffu, s1, 1);
            s1 += __shfl_xor_sync(0xffffffffu, s1, 2);
            l0 = l0*al0 + s0;
            l1 = l1*al1 + s1;
        }
        CP_WAIT0();          // next tile's cp.async chunks landed
        __syncthreads();
        cur ^= 1;
    }

    // ---- epilogue ----
    const float inv0 = 1.0f / l0;
    const float inv1 = 1.0f / l1;
    float* ob0 = out + (size_t)(b*S_LEN + qg0)*QSTRIDE + h*HD;
    float* ob1 = out + (size_t)(b*S_LEN + qg1)*QSTRIDE + h*HD;
    #pragma unroll
    for (int nb = 0; nb < 16; nb++) {
        int col = nb*8 + cq;
        *(float2*)(ob0 + col) = make_float2(oacc[nb][0]*inv0, oacc[nb][1]*inv0);
        *(float2*)(ob1 + col) = make_float2(oacc[nb][2]*inv1, oacc[nb][3]*inv1);
    }

    // stash exact softmax stats (log2-domain m) for the last NTS query rows
    if (q0 == S_LEN - BQ && w >= 4 && (lane & 3) == 0) {
        int base = (b*NH + h)*NTS;
        int r0i  = qg0 - (S_LEN - NTS);
        g_m[base + r0i    ] = m0;
        g_m[base + r0i + 8] = m1;
        g_l[base + r0i    ] = l0;
        g_l[base + r0i + 8] = l1;
    }
}

// ---------------------------------------------------------------------------
// Kernel 2: score_sum[b,h,k] = sum over last 64 queries q>=k of 2^(s-m_q)/l_q.
// Q converted inline from fp32 (identical rounding to kernel 1); K fp16.
// grid (S/256, NH, B), 256 threads (8 warps). Warp w = (wq = w&3, wk = w>>2).
// ---------------------------------------------------------------------------
__global__ void __launch_bounds__(256, 2) score_sum_k(
    const float* __restrict__ qg, float* __restrict__ ssum)
{
    extern __shared__ __align__(16) half sm2[];
    half*  Qs = sm2;                       // 64 x PIT
    half*  Ks = sm2 + 64*PIT;              // BK2 x PIT
    float* ms = (float*)(sm2 + (64+BK2)*PIT);
    float* ws = ms + 64;
    float* part = ws + 64;                 // 8 x 128

    const int tid  = threadIdx.x;
    const int w    = tid >> 5;
    const int lane = tid & 31;
    const int wq   = w & 3;
    const int wk   = w >> 2;
    const int h    = blockIdx.y;
    const int b    = blockIdx.z;
    const int hk   = h >> 2;
    const int k0   = blockIdx.x * BK2;

    {
        const float* qbase = qg + (size_t)(b*S_LEN + (S_LEN - NTS))*QSTRIDE + h*HD;
        #pragma unroll 4
        for (int i = tid; i < 64*32; i += 256) {
            int r = i >> 5, c4 = i & 31;
            float4 t = *(const float4*)(qbase + (size_t)r*QSTRIDE + c4*4);
            *(uint2*)&Qs[r*PIT + c4*4] =
                make_uint2(packh2(t.x*QSC, t.y*QSC), packh2(t.z*QSC, t.w*QSC));
        }
        const __half* kbase = g_kh + (size_t)(b*S_LEN + k0)*KSTRIDE + hk*HD;
        #pragma unroll
        for (int i = tid; i < BK2*16; i += 256) {
            int r = i >> 4, c = i & 15;
            *(uint4*)&Ks[r*PIT + c*8] = *(const uint4*)(kbase + (size_t)r*KSTRIDE + c*8);
        }
        if (tid < 64) {
            int base = (b*NH + h)*NTS;
            ms[tid] = g_m[base + tid];
            ws[tid] = 1.0f / g_l[base + tid];
        }
    }
    __syncthreads();

    unsigned aq[8][4];
    {
        const half* qp = &Qs[(wq*16 + ((lane>>3)&1)*8 + (lane&7))*PIT + (lane>>4)*8];
        #pragma unroll
        for (int kd = 0; kd < 8; kd++)
            ldsm_x4(aq[kd][0], aq[kd][1], aq[kd][2], aq[kd][3], qp + kd*16);
    }

    float sacc[16][4];
    #pragma unroll
    for (int nb = 0; nb < 16; nb++) {
        sacc[nb][0] = 0.f; sacc[nb][1] = 0.f; sacc[nb][2] = 0.f; sacc[nb][3] = 0.f;
    }
    {
        const half* kp = Ks + (wk*128 + (lane>>4)*8 + (lane&7))*PIT + ((lane>>3)&1)*8;
        #pragma unroll
        for (int kd = 0; kd < 8; kd++) {
            #pragma unroll
            for (int nbp = 0; nbp < 8; nbp++) {
                unsigned b0, b1, b2, b3;
                ldsm_x4(b0, b1, b2, b3, kp + nbp*16*PIT + kd*16);
                mma16816(sacc[2*nbp  ][0], sacc[2*nbp  ][1], sacc[2*nbp  ][2], sacc[2*nbp  ][3],
                         aq[kd][0], aq[kd][1], aq[kd][2], aq[kd][3], b0, b1);
                mma16816(sacc[2*nbp+1][0], sacc[2*nbp+1][1], sacc[2*nbp+1][2], sacc[2*nbp+1][3],
                         aq[kd][0], aq[kd][1], aq[kd][2], aq[kd][3], b2, b3);
            }
        }
    }

    const int rq = lane >> 2;
    const int cq = (lane & 3) * 2;
    const float m0 = ms[wq*16 + rq],     m1 = ms[wq*16 + rq + 8];
    const float w0 = ws[wq*16 + rq],     w1 = ws[wq*16 + rq + 8];
    const int  qg0 = S_LEN - NTS + wq*16 + rq, qg1 = qg0 + 8;

    #pragma unroll
    for (int nb = 0; nb < 16; nb++) {
        int c = k0 + wk*128 + nb*8 + cq;
        float e0 = (c     <= qg0) ? ex2f(sacc[nb][0] - m0) * w0 : 0.f;
        float e1 = (c + 1 <= qg0) ? ex2f(sacc[nb][1] - m0) * w0 : 0.f;
        float e2 = (c     <= qg1) ? ex2f(sacc[nb][2] - m1) * w1 : 0.f;
        float e3 = (c + 1 <= qg1) ? ex2f(sacc[nb][3] - m1) * w1 : 0.f;
        float cs0 = e0 + e2, cs1 = e1 + e3;
        cs0 += __shfl_xor_sync(0xffffffffu, cs0, 4);
        cs0 += __shfl_xor_sync(0xffffffffu, cs0, 8);
        cs0 += __shfl_xor_sync(0xffffffffu, cs0, 16);
        cs1 += __shfl_xor_sync(0xffffffffu, cs1, 4);
        cs1 += __shfl_xor_sync(0xffffffffu, cs1, 8);
        cs1 += __shfl_xor_sync(0xffffffffu, cs1, 16);
        if (lane < 4) {
            part[w*128 + nb*8 + cq    ] = cs0;
            part[w*128 + nb*8 + cq + 1] = cs1;
        }
    }
    __syncthreads();

    const int grp = tid >> 7, kl = tid & 127;
    float s = part[(grp*4+0)*128 + kl] + part[(grp*4+1)*128 + kl]
            + part[(grp*4+2)*128 + kl] + part[(grp*4+3)*128 + kl];
    ssum[((size_t)b*NH + h)*S_LEN + k0 + tid] = s;
}

// ---------------------------------------------------------------------------
extern "C" void kernel_launch(void* const* d_in, const int* in_sizes, int n_in,
                              void* d_out, int out_size)
{
    const float* q = (const float*)d_in[0];
    const float* k = (const float*)d_in[1];
    const float* v = (const float*)d_in[2];

    float* out  = (float*)d_out;
    float* ssum = out + (size_t)B_SZ * S_LEN * QSTRIDE;

    cudaFuncSetAttribute(flash_fwd,   cudaFuncAttributeMaxDynamicSharedMemorySize, SMEM1);
    cudaFuncSetAttribute(score_sum_k, cudaFuncAttributeMaxDynamicSharedMemorySize, SMEM2);

    prepass<<<NKH/4/256, 256>>>(k, v);

    dim3 g1(S_LEN/BQ, NH, B_SZ);
    flash_fwd<<<g1, 256, SMEM1>>>(q, out);

    dim3 g2(S_LEN/BK2, NH, B_SZ);
    score_sum_k<<<g2, 256, SMEM2>>>(q, ssum);
}